// round 14
// baseline (speedup 1.0000x reference)
#include <cuda_runtime.h>
#include <cuda_bf16.h>
#include <mma.h>
#include <math.h>
#include <float.h>
#include <stdint.h>

using namespace nvcuda;

// Problem constants
#define NQ_TOT   25216
#define NQ_CL    128
#define NQ_FT    25088
#define CDIM     768
#define KCB      4096
#define KTOT     8192
#define TOPK     3
#define NCAND    16

// Output offsets (flattened tuple, all float32)
#define OFF_LOSS    0LL
#define OFF_QUANT   1LL
#define OFF_CLPERP  58097665LL
#define OFF_FTPERP  58097666LL
#define OFF_CLAVG   58097667LL
#define OFF_FTAVG   58101763LL
#define OFF_IDX     58105859LL
#define OFF_DIST    58181507LL   // not 16B-aligned: scalar access only in dist region

// ---------------------------------------------------------------------------
// Scratch (device globals — no allocation allowed)
__device__ __nv_bfloat16 g_qbf[(size_t)NQ_TOT * CDIM];
__device__ __nv_bfloat16 g_cbf[(size_t)KCB * CDIM];
__device__ __nv_bfloat16 g_fbf[(size_t)KCB * CDIM];
__device__ float  g_qnorm[NQ_TOT];
__device__ float  g_enorm[KTOT];          // [0..4095]=class, [4096..]=feat
__device__ int    g_cand[NQ_TOT * NCAND]; // approx top-16 raw indices
__device__ float  g_rd[NQ_TOT * NCAND];   // exact fp32 rescored distances
__device__ int    g_idx[NQ_TOT * TOPK];   // exact top-3 raw indices
__device__ float  g_cnt[KTOT];
__device__ double g_loss[2];

// ---------------------------------------------------------------------------
__device__ __forceinline__ void cp16(void* s, const void* g) {
    uint32_t sa = (uint32_t)__cvta_generic_to_shared(s);
    asm volatile("cp.async.cg.shared.global [%0], [%1], 16;" :: "r"(sa), "l"(g));
}
#define CP_COMMIT() asm volatile("cp.async.commit_group;" ::: "memory")
#define CP_WAIT2()  asm volatile("cp.async.wait_group 2;" ::: "memory")

// ---------------------------------------------------------------------------
__global__ void init_kernel() {
    int t = blockIdx.x * blockDim.x + threadIdx.x;
    if (t < KTOT) g_cnt[t] = 0.0f;
    if (t < 2) g_loss[t] = 0.0;
}

// Fused: fp32 -> bf16 conversion AND row L2-norms (one read pass).
__global__ void conv_norms_kernel(const float* __restrict__ feats,
                                  const float* __restrict__ clsE,
                                  const float* __restrict__ ftE) {
    int row = blockIdx.x;
    const float* src; float* ndst; __nv_bfloat16* bdst;
    if (row < NQ_TOT) {
        src = feats + (size_t)row * CDIM; ndst = g_qnorm + row; bdst = g_qbf + (size_t)row * CDIM;
    } else if (row < NQ_TOT + KCB) {
        int r = row - NQ_TOT;
        src = clsE + (size_t)r * CDIM; ndst = g_enorm + r; bdst = g_cbf + (size_t)r * CDIM;
    } else {
        int r = row - NQ_TOT - KCB;
        src = ftE + (size_t)r * CDIM; ndst = g_enorm + KCB + r; bdst = g_fbf + (size_t)r * CDIM;
    }
    int t = threadIdx.x;  // 256
    float s = 0.f;
    #pragma unroll
    for (int i = t; i < CDIM; i += 256) {
        float v = src[i];
        bdst[i] = __float2bfloat16(v);
        s = fmaf(v, v, s);
    }
    __shared__ float red[256];
    red[t] = s; __syncthreads();
    for (int st = 128; st > 0; st >>= 1) { if (t < st) red[t] += red[t + st]; __syncthreads(); }
    if (t == 0) *ndst = red[0];
}

// ---------------------------------------------------------------------------
// bf16 WMMA GEMM + distance epilogue + fused FLT_MAX padding fill.
// grid (197, 16): bm==0 -> class tile, bm>=1 -> feat tile.
// CTA tile 128x256, 8 warps (64x64 warp tile: wm=wid&1, wn=wid>>1),
// BK=32, cp.async 4-stage (3 in flight). 1 CTA/SM (120KB smem).
#define BK      32
#define LDS_    40      // bf16 row stride (80B, 16B-aligned)
#define NCHK    (CDIM / BK)   // 24
#define A_BYTES 10240   // 128 rows * 80B
#define B_BYTES 20480   // 256 rows * 80B
#define STAGEB  (A_BYTES + B_BYTES)   // 30720
#define NSTAGE  4

__global__ void __launch_bounds__(256, 1)
gemm_wmma(const __nv_bfloat16* __restrict__ Q,
          const __nv_bfloat16* __restrict__ Ccls,
          const __nv_bfloat16* __restrict__ Cft,
          const float* __restrict__ qn, const float* __restrict__ en,
          float* __restrict__ dist /* out + OFF_DIST */)
{
    extern __shared__ char smem[];
    const int tid = threadIdx.x;
    const int wid = tid >> 5;
    const int bm = blockIdx.x, bn = blockIdx.y;
    const int wm = wid & 1;     // 2 row groups of 64
    const int wn = wid >> 1;    // 4 col groups of 64

    const __nv_bfloat16* Abase = Q + (size_t)bm * 128 * CDIM;
    const __nv_bfloat16* Bbase = ((bm == 0) ? Ccls : Cft) + (size_t)bn * 256 * CDIM;
    const int colOff = (bm == 0) ? 0 : KCB;

    // load maps: A = 512 uint4 (2/thread), B = 1024 uint4 (4/thread)
    int arow[2], ac8[2], brow[4], bc8[4];
    #pragma unroll
    for (int v = 0; v < 2; v++) { int u = tid + v * 256; arow[v] = u >> 2; ac8[v] = u & 3; }
    #pragma unroll
    for (int v = 0; v < 4; v++) { int u = tid + v * 256; brow[v] = u >> 2; bc8[v] = u & 3; }

    wmma::fragment<wmma::accumulator, 16, 16, 16, float> acc[4][4];
    #pragma unroll
    for (int i = 0; i < 4; i++)
        #pragma unroll
        for (int j = 0; j < 4; j++) wmma::fill_fragment(acc[i][j], 0.0f);

    // prefetch stages 0..2
    #pragma unroll
    for (int p = 0; p < 3; p++) {
        char* sA = smem + p * STAGEB;
        char* sB = sA + A_BYTES;
        const int kk = p * BK;
        #pragma unroll
        for (int v = 0; v < 2; v++)
            cp16(sA + (arow[v] * LDS_ + ac8[v] * 8) * 2, Abase + (size_t)arow[v] * CDIM + kk + ac8[v] * 8);
        #pragma unroll
        for (int v = 0; v < 4; v++)
            cp16(sB + (brow[v] * LDS_ + bc8[v] * 8) * 2, Bbase + (size_t)brow[v] * CDIM + kk + bc8[v] * 8);
        CP_COMMIT();
    }

    for (int c = 0; c < NCHK; c++) {
        const int s = c % NSTAGE;
        CP_WAIT2();           // stage c's group complete (<=2 groups pending)
        __syncthreads();

        __nv_bfloat16* sA = (__nv_bfloat16*)(smem + s * STAGEB);
        __nv_bfloat16* sB = (__nv_bfloat16*)(smem + s * STAGEB + A_BYTES);

        #pragma unroll
        for (int kk = 0; kk < BK / 16; kk++) {
            wmma::fragment<wmma::matrix_a, 16, 16, 16, __nv_bfloat16, wmma::row_major> af[4];
            wmma::fragment<wmma::matrix_b, 16, 16, 16, __nv_bfloat16, wmma::col_major> bf[4];
            #pragma unroll
            for (int i = 0; i < 4; i++)
                wmma::load_matrix_sync(af[i], sA + (wm * 64 + i * 16) * LDS_ + kk * 16, LDS_);
            #pragma unroll
            for (int j = 0; j < 4; j++)
                wmma::load_matrix_sync(bf[j], sB + (wn * 64 + j * 16) * LDS_ + kk * 16, LDS_);
            #pragma unroll
            for (int i = 0; i < 4; i++)
                #pragma unroll
                for (int j = 0; j < 4; j++)
                    wmma::mma_sync(acc[i][j], af[i], bf[j], acc[i][j]);
        }

        if (c + 3 < NCHK) {
            const int ns = (c + 3) % NSTAGE;
            char* nA = smem + ns * STAGEB;
            char* nB = nA + A_BYTES;
            const int kk = (c + 3) * BK;
            #pragma unroll
            for (int v = 0; v < 2; v++)
                cp16(nA + (arow[v] * LDS_ + ac8[v] * 8) * 2, Abase + (size_t)arow[v] * CDIM + kk + ac8[v] * 8);
            #pragma unroll
            for (int v = 0; v < 4; v++)
                cp16(nB + (brow[v] * LDS_ + bc8[v] * 8) * 2, Bbase + (size_t)brow[v] * CDIM + kk + bc8[v] * 8);
        }
        CP_COMMIT();          // one group per iteration keeps the count model
    }

    // Epilogue: two 128-col halves via smem transpose (f32, ld=132)
    float* sf = (float*)smem;   // 128*132*4 = 67584 <= 122880
    #pragma unroll
    for (int h = 0; h < 2; h++) {
        __syncthreads();      // sf free (K-loop done / previous half read)
        if ((wn >> 1) == h) {
            #pragma unroll
            for (int i = 0; i < 4; i++)
                #pragma unroll
                for (int j = 0; j < 4; j++)
                    wmma::store_matrix_sync(sf + (size_t)(wm * 64 + i * 16) * 132 + (wn & 1) * 64 + j * 16,
                                            acc[i][j], 132, wmma::mem_row_major);
        }
        __syncthreads();

        const int colL = tid & 127;
        const int colG = bn * 256 + h * 128 + colL;   // codebook-local column
        const float env = en[colOff + colG];
        const long long cReal = (long long)(colOff + colG);
        const long long cPad  = (long long)((colOff ^ KCB) + colG);
        #pragma unroll 4
        for (int r = tid >> 7; r < 128; r += 2) {
            const long long rbase = (long long)(bm * 128 + r) * KTOT;
            dist[rbase + cReal] = qn[bm * 128 + r] + env - 2.0f * sf[(size_t)r * 132 + colL];
            dist[rbase + cPad]  = FLT_MAX;
        }
    }
}

// ---------------------------------------------------------------------------
// Approximate top-16 per query row, u32 packed keys.
// key = (dist_bits & 0xFFFFF000) | idx. Positive fp32: bit order == numeric
// order; 12-bit mantissa truncation noise is absorbed by the exact rescore.
__global__ void __launch_bounds__(128)
topk_kernel(const float* __restrict__ out) {
    int q = blockIdx.x;
    int t = threadIdx.x;
    const float* row = out + OFF_DIST + (long long)q * KTOT + (q < NQ_CL ? 0 : KCB);

    unsigned key[32];
    #pragma unroll
    for (int j = 0; j < 32; j++) {
        unsigned vb = __float_as_uint(row[j * 128 + t]);
        key[j] = (vb & 0xFFFFF000u) | (unsigned)(j * 128 + t);
    }
    unsigned lm = key[0];
    #pragma unroll
    for (int j = 1; j < 32; j++) lm = min(lm, key[j]);

    __shared__ unsigned wmin[4];
    __shared__ unsigned win;

    for (int sel = 0; sel < NCAND; sel++) {
        unsigned m = lm;
        #pragma unroll
        for (int o = 16; o; o >>= 1)
            m = min(m, __shfl_xor_sync(0xffffffffu, m, o));
        if ((t & 31) == 0) wmin[t >> 5] = m;
        __syncthreads();
        if (t == 0) {
            unsigned mm = min(min(wmin[0], wmin[1]), min(wmin[2], wmin[3]));
            win = mm;
            g_cand[q * NCAND + sel] = (int)(mm & 0xFFFu);
        }
        __syncthreads();
        unsigned widx = win & 0xFFFu;
        if ((widx & 127u) == (unsigned)t) {
            key[widx >> 7] = 0xFFFFFFFFu;
            lm = key[0];
            #pragma unroll
            for (int j = 1; j < 32; j++) lm = min(lm, key[j]);
        }
    }
}

// ---------------------------------------------------------------------------
// Exact fp32 rescore: sequential fmaf over k in index order — bit-identical
// to the fp32 GEMM ordering that matched jax exactly.
__global__ void __launch_bounds__(256)
rescore_pairs(const float* __restrict__ feats,
              const float* __restrict__ clsE, const float* __restrict__ ftE) {
    int g = blockIdx.x * 256 + threadIdx.x;
    if (g >= NQ_TOT * NCAND) return;
    int q = g / NCAND;
    int cand = g_cand[g];
    const float4* x = (const float4*)(feats + (size_t)q * CDIM);
    const float4* e = (const float4*)((q < NQ_CL ? clsE : ftE) + (size_t)cand * CDIM);
    float s = 0.f;
    #pragma unroll 8
    for (int i = 0; i < CDIM / 4; i++) {
        float4 a = x[i], b = e[i];
        s = fmaf(a.x, b.x, s);
        s = fmaf(a.y, b.y, s);
        s = fmaf(a.z, b.z, s);
        s = fmaf(a.w, b.w, s);
    }
    g_rd[g] = (g_qnorm[q] + g_enorm[(q < NQ_CL ? 0 : KCB) + cand]) - 2.f * s;
}

// Final top-3 from exact distances, lower-index tie-break; counts + idx output
__global__ void __launch_bounds__(256)
select_kernel(float* __restrict__ out) {
    int q = blockIdx.x * 256 + threadIdx.x;
    if (q >= NQ_TOT) return;
    float d[NCAND]; int id[NCAND]; bool used[NCAND];
    #pragma unroll
    for (int c = 0; c < NCAND; c++) {
        d[c] = g_rd[q * NCAND + c];
        id[c] = g_cand[q * NCAND + c];
        used[c] = false;
    }
    int base = (q < NQ_CL ? 0 : KCB);
    for (int sel = 0; sel < TOPK; sel++) {
        float bv = FLT_MAX; int bi = 0x7fffffff; int bw = 0;
        #pragma unroll
        for (int c = 0; c < NCAND; c++) {
            if (used[c]) continue;
            if (d[c] < bv || (d[c] == bv && id[c] < bi)) { bv = d[c]; bi = id[c]; bw = c; }
        }
        used[bw] = true;
        g_idx[q * TOPK + sel] = bi;
        out[OFF_IDX + q * TOPK + sel] = (float)(bi + base);
        atomicAdd(&g_cnt[base + bi], 1.0f);
    }
}

// Gather quantized = emb[idx] + commitment-loss sums. One WARP per gather
// (8 gathers/block): 8x fewer blocks and 8x fewer global double atomics.
__global__ void __launch_bounds__(256)
gather_loss(const float* __restrict__ feats,
            const float* __restrict__ clsE, const float* __restrict__ ftE,
            float* __restrict__ outQ) {
    int wid  = threadIdx.x >> 5;
    int lane = threadIdx.x & 31;
    int g = blockIdx.x * 8 + wid;         // 75648 = 9456*8 exactly
    int q = g / TOPK;
    int idx = g_idx[g];
    const float* x = feats + (size_t)q * CDIM;
    const float* e = (q < NQ_CL ? clsE : ftE) + (size_t)idx * CDIM;
    float s = 0.f;
    #pragma unroll
    for (int i = lane; i < CDIM; i += 32) {
        float ev = e[i];
        float d = ev - x[i];
        outQ[(size_t)g * CDIM + i] = ev;
        s = fmaf(d, d, s);
    }
    #pragma unroll
    for (int o = 16; o; o >>= 1) s += __shfl_xor_sync(0xffffffffu, s, o);

    __shared__ float ws[8];
    __shared__ int   wb[8];
    if (lane == 0) { ws[wid] = s; wb[wid] = (q < NQ_CL) ? 0 : 1; }
    __syncthreads();
    if (threadIdx.x == 0) {
        double s0 = 0.0, s1 = 0.0; bool h0 = false, h1 = false;
        #pragma unroll
        for (int w = 0; w < 8; w++) {
            if (wb[w]) { s1 += (double)ws[w]; h1 = true; }
            else       { s0 += (double)ws[w]; h0 = true; }
        }
        if (h0) atomicAdd(&g_loss[0], s0);
        if (h1) atomicAdd(&g_loss[1], s1);
    }
}

// avg_probs, perplexities, loss scalar
__global__ void __launch_bounds__(1024)
finalize_kernel(float* __restrict__ out) {
    int b = blockIdx.x;
    int t = threadIdx.x;
    float N = (b == 0) ? (float)NQ_CL : (float)NQ_FT;
    float* avg = out + (b == 0 ? OFF_CLAVG : OFF_FTAVG);
    float ent = 0.f;
    for (int i = t; i < KCB; i += 1024) {
        float p = g_cnt[b * KCB + i] / N;
        avg[i] = p;
        ent += p * logf(p + 1e-10f);
    }
    __shared__ float red[1024];
    red[t] = ent; __syncthreads();
    for (int st = 512; st > 0; st >>= 1) { if (t < st) red[t] += red[t + st]; __syncthreads(); }
    if (t == 0) {
        out[b == 0 ? OFF_CLPERP : OFF_FTPERP] = expf(-red[0]);
        if (b == 0) {
            double mcl = g_loss[0] / ((double)NQ_CL * TOPK * CDIM);
            double mft = g_loss[1] / ((double)NQ_FT * TOPK * CDIM);
            out[OFF_LOSS] = (float)(0.25 * mft + 0.25 * mcl);
        }
    }
}

// ---------------------------------------------------------------------------
extern "C" void kernel_launch(void* const* d_in, const int* in_sizes, int n_in,
                              void* d_out, int out_size) {
    const float* feats = (const float*)d_in[0];   // (197,128,768)
    const float* clsE  = (const float*)d_in[1];   // (4096,768)
    const float* ftE   = (const float*)d_in[2];   // (4096,768)
    float* out = (float*)d_out;

    const int SMEM_GEMM = NSTAGE * STAGEB;   // 122880
    cudaFuncSetAttribute(gemm_wmma, cudaFuncAttributeMaxDynamicSharedMemorySize, SMEM_GEMM);

    init_kernel<<<(KTOT + 255) / 256, 256>>>();
    conv_norms_kernel<<<NQ_TOT + 2 * KCB, 256>>>(feats, clsE, ftE);

    __nv_bfloat16 *qbf, *cbf, *fbf;
    float *qnorm, *enorm;
    cudaGetSymbolAddress((void**)&qbf, g_qbf);
    cudaGetSymbolAddress((void**)&cbf, g_cbf);
    cudaGetSymbolAddress((void**)&fbf, g_fbf);
    cudaGetSymbolAddress((void**)&qnorm, g_qnorm);
    cudaGetSymbolAddress((void**)&enorm, g_enorm);

    // Unified GEMM: bm 0 = class tile, bm 1..196 = feat tiles; 256-col N tiles.
    gemm_wmma<<<dim3(197, 16), 256, SMEM_GEMM>>>(
        qbf, cbf, fbf, qnorm, enorm, out + OFF_DIST);

    topk_kernel<<<NQ_TOT, 128>>>(out);
    rescore_pairs<<<(NQ_TOT * NCAND + 255) / 256, 256>>>(feats, clsE, ftE);
    select_kernel<<<(NQ_TOT + 255) / 256, 256>>>(out);
    gather_loss<<<NQ_TOT * TOPK / 8, 256>>>(feats, clsE, ftE, out + OFF_QUANT);
    finalize_kernel<<<2, 1024>>>(out);
}

// round 15
// speedup vs baseline: 1.0802x; 1.0802x over previous
#include <cuda_runtime.h>
#include <cuda_bf16.h>
#include <mma.h>
#include <math.h>
#include <float.h>
#include <stdint.h>

using namespace nvcuda;

// Problem constants
#define NQ_TOT   25216
#define NQ_CL    128
#define NQ_FT    25088
#define CDIM     768
#define KCB      4096
#define KTOT     8192
#define TOPK     3
#define NCAND    16

// Output offsets (flattened tuple, all float32)
#define OFF_LOSS    0LL
#define OFF_QUANT   1LL
#define OFF_CLPERP  58097665LL
#define OFF_FTPERP  58097666LL
#define OFF_CLAVG   58097667LL
#define OFF_FTAVG   58101763LL
#define OFF_IDX     58105859LL
#define OFF_DIST    58181507LL   // not 16B-aligned: scalar access only in dist region

// ---------------------------------------------------------------------------
// Scratch (device globals — no allocation allowed)
__device__ __nv_bfloat16 g_qbf[(size_t)NQ_TOT * CDIM];
__device__ __nv_bfloat16 g_cbf[(size_t)KCB * CDIM];
__device__ __nv_bfloat16 g_fbf[(size_t)KCB * CDIM];
__device__ float  g_qnorm[NQ_TOT];
__device__ float  g_enorm[KTOT];          // [0..4095]=class, [4096..]=feat
__device__ int    g_cand[NQ_TOT * NCAND]; // approx top-16 raw indices
__device__ float  g_rd[NQ_TOT * NCAND];   // exact fp32 rescored distances
__device__ int    g_idx[NQ_TOT * TOPK];   // exact top-3 raw indices
__device__ float  g_cnt[KTOT];
__device__ double g_loss[2];

// ---------------------------------------------------------------------------
__device__ __forceinline__ void cp16(void* s, const void* g) {
    uint32_t sa = (uint32_t)__cvta_generic_to_shared(s);
    asm volatile("cp.async.cg.shared.global [%0], [%1], 16;" :: "r"(sa), "l"(g));
}
#define CP_COMMIT() asm volatile("cp.async.commit_group;" ::: "memory")
#define CP_WAIT1()  asm volatile("cp.async.wait_group 1;" ::: "memory")

// ---------------------------------------------------------------------------
__global__ void init_kernel() {
    int t = blockIdx.x * blockDim.x + threadIdx.x;
    if (t < KTOT) g_cnt[t] = 0.0f;
    if (t < 2) g_loss[t] = 0.0;
}

// Fused: fp32 -> bf16 conversion AND row L2-norms (one read pass).
__global__ void conv_norms_kernel(const float* __restrict__ feats,
                                  const float* __restrict__ clsE,
                                  const float* __restrict__ ftE) {
    int row = blockIdx.x;
    const float* src; float* ndst; __nv_bfloat16* bdst;
    if (row < NQ_TOT) {
        src = feats + (size_t)row * CDIM; ndst = g_qnorm + row; bdst = g_qbf + (size_t)row * CDIM;
    } else if (row < NQ_TOT + KCB) {
        int r = row - NQ_TOT;
        src = clsE + (size_t)r * CDIM; ndst = g_enorm + r; bdst = g_cbf + (size_t)r * CDIM;
    } else {
        int r = row - NQ_TOT - KCB;
        src = ftE + (size_t)r * CDIM; ndst = g_enorm + KCB + r; bdst = g_fbf + (size_t)r * CDIM;
    }
    int t = threadIdx.x;  // 256
    float s = 0.f;
    #pragma unroll
    for (int i = t; i < CDIM; i += 256) {
        float v = src[i];
        bdst[i] = __float2bfloat16(v);
        s = fmaf(v, v, s);
    }
    __shared__ float red[256];
    red[t] = s; __syncthreads();
    for (int st = 128; st > 0; st >>= 1) { if (t < st) red[t] += red[t + st]; __syncthreads(); }
    if (t == 0) *ndst = red[0];
}

// ---------------------------------------------------------------------------
// bf16 WMMA GEMM + distance epilogue + fused FLT_MAX padding fill.
// grid (197, 32): bm==0 -> class tile, bm>=1 -> feat tile.
// CTA tile 128x128, 4 warps (64x64 warp tile), BK=32, cp.async 3-stage,
// 2 CTAs/SM (R13 config — co-residency beats traffic reduction here).
#define BK     32
#define LDS_   40     // bf16 row stride (80B, 16B-aligned)
#define NCHK   (CDIM / BK)   // 24
#define STAGEB 20480  // bytes per stage (A 10240 + B 10240)

__global__ void __launch_bounds__(128, 2)
gemm_wmma(const __nv_bfloat16* __restrict__ Q,
          const __nv_bfloat16* __restrict__ Ccls,
          const __nv_bfloat16* __restrict__ Cft,
          const float* __restrict__ qn, const float* __restrict__ en,
          float* __restrict__ dist /* out + OFF_DIST */)
{
    extern __shared__ char smem[];
    const int tid = threadIdx.x;
    const int wid = tid >> 5;
    const int bm = blockIdx.x, bn = blockIdx.y;
    const int wm = wid & 1;
    const int wn = wid >> 1;

    const __nv_bfloat16* Abase = Q + (size_t)bm * 128 * CDIM;
    const __nv_bfloat16* Bbase = ((bm == 0) ? Ccls : Cft) + (size_t)bn * 128 * CDIM;
    const int colOff = (bm == 0) ? 0 : KCB;

    int lrow[4], lc8[4];
    #pragma unroll
    for (int v = 0; v < 4; v++) { int u = tid + v * 128; lrow[v] = u >> 2; lc8[v] = u & 3; }

    wmma::fragment<wmma::accumulator, 16, 16, 16, float> acc[4][4];
    #pragma unroll
    for (int i = 0; i < 4; i++)
        #pragma unroll
        for (int j = 0; j < 4; j++) wmma::fill_fragment(acc[i][j], 0.0f);

    #pragma unroll
    for (int p = 0; p < 2; p++) {
        char* sA = smem + p * STAGEB;
        char* sB = sA + 10240;
        const int kk = p * BK;
        #pragma unroll
        for (int v = 0; v < 4; v++) {
            cp16(sA + (lrow[v] * LDS_ + lc8[v] * 8) * 2, Abase + (size_t)lrow[v] * CDIM + kk + lc8[v] * 8);
            cp16(sB + (lrow[v] * LDS_ + lc8[v] * 8) * 2, Bbase + (size_t)lrow[v] * CDIM + kk + lc8[v] * 8);
        }
        CP_COMMIT();
    }

    for (int c = 0; c < NCHK; c++) {
        const int s = c % 3;
        CP_WAIT1();
        __syncthreads();

        __nv_bfloat16* sA = (__nv_bfloat16*)(smem + s * STAGEB);
        __nv_bfloat16* sB = (__nv_bfloat16*)(smem + s * STAGEB + 10240);

        #pragma unroll
        for (int kk = 0; kk < BK / 16; kk++) {
            wmma::fragment<wmma::matrix_a, 16, 16, 16, __nv_bfloat16, wmma::row_major> af[4];
            wmma::fragment<wmma::matrix_b, 16, 16, 16, __nv_bfloat16, wmma::col_major> bf[4];
            #pragma unroll
            for (int i = 0; i < 4; i++)
                wmma::load_matrix_sync(af[i], sA + (wm * 64 + i * 16) * LDS_ + kk * 16, LDS_);
            #pragma unroll
            for (int j = 0; j < 4; j++)
                wmma::load_matrix_sync(bf[j], sB + (wn * 64 + j * 16) * LDS_ + kk * 16, LDS_);
            #pragma unroll
            for (int i = 0; i < 4; i++)
                #pragma unroll
                for (int j = 0; j < 4; j++)
                    wmma::mma_sync(acc[i][j], af[i], bf[j], acc[i][j]);
        }

        if (c + 2 < NCHK) {
            const int ns = (c + 2) % 3;
            char* nA = smem + ns * STAGEB;
            char* nB = nA + 10240;
            const int kk = (c + 2) * BK;
            #pragma unroll
            for (int v = 0; v < 4; v++) {
                cp16(nA + (lrow[v] * LDS_ + lc8[v] * 8) * 2, Abase + (size_t)lrow[v] * CDIM + kk + lc8[v] * 8);
                cp16(nB + (lrow[v] * LDS_ + lc8[v] * 8) * 2, Bbase + (size_t)lrow[v] * CDIM + kk + lc8[v] * 8);
            }
        }
        CP_COMMIT();
    }
    __syncthreads();

    // Epilogue: acc -> smem (f32, ld=132) -> coalesced scalar stores + padding
    float* sf = (float*)smem;   // 128*132*4 = 67584 bytes
    #pragma unroll
    for (int i = 0; i < 4; i++)
        #pragma unroll
        for (int j = 0; j < 4; j++)
            wmma::store_matrix_sync(sf + (size_t)(wm * 64 + i * 16) * 132 + wn * 64 + j * 16,
                                    acc[i][j], 132, wmma::mem_row_major);
    __syncthreads();

    const int colL = tid;
    const int colG = bn * 128 + colL;
    const float env = en[colOff + colG];
    const long long cReal = (long long)(colOff + colG);
    const long long cPad  = (long long)((colOff ^ KCB) + colG);
    #pragma unroll 4
    for (int r = 0; r < 128; r++) {
        const long long rbase = (long long)(bm * 128 + r) * KTOT;
        dist[rbase + cReal] = qn[bm * 128 + r] + env - 2.0f * sf[(size_t)r * 132 + colL];
        dist[rbase + cPad]  = FLT_MAX;
    }
}

// ---------------------------------------------------------------------------
// Approximate top-16 per query row, u32 packed keys, warp-local selection.
// key = (dist_bits & 0xFFFFF000) | idx (positive fp32: bit order == numeric
// order; truncation noise absorbed by exact rescore; u32 min == lower-index
// tie-break). Each warp owns a 1024-col strip and extracts its local top-16
// with pure shuffle reductions (no block syncs); warp 0 then merges 4x16
// candidates. Global top-16 is a subset of the union of warp top-16s.
__global__ void __launch_bounds__(128)
topk_kernel(const float* __restrict__ out) {
    int q = blockIdx.x;
    int t = threadIdx.x;
    int w = t >> 5, lane = t & 31;
    const float* row = out + OFF_DIST + (long long)q * KTOT + (q < NQ_CL ? 0 : KCB);

    unsigned key[32];
    #pragma unroll
    for (int j = 0; j < 32; j++) {
        int idx = w * 1024 + j * 32 + lane;
        unsigned vb = __float_as_uint(row[idx]);
        key[j] = (vb & 0xFFFFF000u) | (unsigned)idx;
    }
    unsigned lm = key[0];
    #pragma unroll
    for (int j = 1; j < 32; j++) lm = min(lm, key[j]);

    __shared__ unsigned cands[64];

    // Phase 1: warp-local top-16 (no block synchronization)
    for (int sel = 0; sel < NCAND; sel++) {
        unsigned m = lm;
        #pragma unroll
        for (int o = 16; o; o >>= 1)
            m = min(m, __shfl_xor_sync(0xffffffffu, m, o));   // all lanes hold min
        if (lane == 0) cands[w * NCAND + sel] = m;
        unsigned widx = m & 0xFFFu;                           // global col idx
        if ((widx & 31u) == (unsigned)lane) {                 // owner lane
            int jw = (int)((widx >> 5) & 31u);
            #pragma unroll
            for (int j = 0; j < 32; j++) if (j == jw) key[j] = 0xFFFFFFFFu;
            lm = key[0];
            #pragma unroll
            for (int j = 1; j < 32; j++) lm = min(lm, key[j]);
        }
    }
    __syncthreads();

    // Phase 2: warp 0 merges 64 candidates (2 per lane, keys unique)
    if (w == 0) {
        unsigned k0 = cands[lane];
        unsigned k1 = cands[32 + lane];
        for (int sel = 0; sel < NCAND; sel++) {
            unsigned m = min(k0, k1);
            #pragma unroll
            for (int o = 16; o; o >>= 1)
                m = min(m, __shfl_xor_sync(0xffffffffu, m, o));
            if (lane == 0) g_cand[q * NCAND + sel] = (int)(m & 0xFFFu);
            if (k0 == m) k0 = 0xFFFFFFFFu;
            if (k1 == m) k1 = 0xFFFFFFFFu;
        }
    }
}

// ---------------------------------------------------------------------------
// Exact fp32 rescore: sequential fmaf over k in index order — bit-identical
// to the fp32 GEMM ordering that matched jax exactly.
__global__ void __launch_bounds__(256)
rescore_pairs(const float* __restrict__ feats,
              const float* __restrict__ clsE, const float* __restrict__ ftE) {
    int g = blockIdx.x * 256 + threadIdx.x;
    if (g >= NQ_TOT * NCAND) return;
    int q = g / NCAND;
    int cand = g_cand[g];
    const float4* x = (const float4*)(feats + (size_t)q * CDIM);
    const float4* e = (const float4*)((q < NQ_CL ? clsE : ftE) + (size_t)cand * CDIM);
    float s = 0.f;
    #pragma unroll 8
    for (int i = 0; i < CDIM / 4; i++) {
        float4 a = x[i], b = e[i];
        s = fmaf(a.x, b.x, s);
        s = fmaf(a.y, b.y, s);
        s = fmaf(a.z, b.z, s);
        s = fmaf(a.w, b.w, s);
    }
    g_rd[g] = (g_qnorm[q] + g_enorm[(q < NQ_CL ? 0 : KCB) + cand]) - 2.f * s;
}

// Final top-3 from exact distances, lower-index tie-break; counts + idx output
__global__ void __launch_bounds__(256)
select_kernel(float* __restrict__ out) {
    int q = blockIdx.x * 256 + threadIdx.x;
    if (q >= NQ_TOT) return;
    float d[NCAND]; int id[NCAND]; bool used[NCAND];
    #pragma unroll
    for (int c = 0; c < NCAND; c++) {
        d[c] = g_rd[q * NCAND + c];
        id[c] = g_cand[q * NCAND + c];
        used[c] = false;
    }
    int base = (q < NQ_CL ? 0 : KCB);
    for (int sel = 0; sel < TOPK; sel++) {
        float bv = FLT_MAX; int bi = 0x7fffffff; int bw = 0;
        #pragma unroll
        for (int c = 0; c < NCAND; c++) {
            if (used[c]) continue;
            if (d[c] < bv || (d[c] == bv && id[c] < bi)) { bv = d[c]; bi = id[c]; bw = c; }
        }
        used[bw] = true;
        g_idx[q * TOPK + sel] = bi;
        out[OFF_IDX + q * TOPK + sel] = (float)(bi + base);
        atomicAdd(&g_cnt[base + bi], 1.0f);
    }
}

// Gather quantized = emb[idx] + commitment-loss sums. One WARP per gather.
__global__ void __launch_bounds__(256)
gather_loss(const float* __restrict__ feats,
            const float* __restrict__ clsE, const float* __restrict__ ftE,
            float* __restrict__ outQ) {
    int wid  = threadIdx.x >> 5;
    int lane = threadIdx.x & 31;
    int g = blockIdx.x * 8 + wid;         // 75648 = 9456*8 exactly
    int q = g / TOPK;
    int idx = g_idx[g];
    const float* x = feats + (size_t)q * CDIM;
    const float* e = (q < NQ_CL ? clsE : ftE) + (size_t)idx * CDIM;
    float s = 0.f;
    #pragma unroll
    for (int i = lane; i < CDIM; i += 32) {
        float ev = e[i];
        float d = ev - x[i];
        outQ[(size_t)g * CDIM + i] = ev;
        s = fmaf(d, d, s);
    }
    #pragma unroll
    for (int o = 16; o; o >>= 1) s += __shfl_xor_sync(0xffffffffu, s, o);

    __shared__ float ws[8];
    __shared__ int   wb[8];
    if (lane == 0) { ws[wid] = s; wb[wid] = (q < NQ_CL) ? 0 : 1; }
    __syncthreads();
    if (threadIdx.x == 0) {
        double s0 = 0.0, s1 = 0.0; bool h0 = false, h1 = false;
        #pragma unroll
        for (int w = 0; w < 8; w++) {
            if (wb[w]) { s1 += (double)ws[w]; h1 = true; }
            else       { s0 += (double)ws[w]; h0 = true; }
        }
        if (h0) atomicAdd(&g_loss[0], s0);
        if (h1) atomicAdd(&g_loss[1], s1);
    }
}

// avg_probs, perplexities, loss scalar
__global__ void __launch_bounds__(1024)
finalize_kernel(float* __restrict__ out) {
    int b = blockIdx.x;
    int t = threadIdx.x;
    float N = (b == 0) ? (float)NQ_CL : (float)NQ_FT;
    float* avg = out + (b == 0 ? OFF_CLAVG : OFF_FTAVG);
    float ent = 0.f;
    for (int i = t; i < KCB; i += 1024) {
        float p = g_cnt[b * KCB + i] / N;
        avg[i] = p;
        ent += p * logf(p + 1e-10f);
    }
    __shared__ float red[1024];
    red[t] = ent; __syncthreads();
    for (int st = 512; st > 0; st >>= 1) { if (t < st) red[t] += red[t + st]; __syncthreads(); }
    if (t == 0) {
        out[b == 0 ? OFF_CLPERP : OFF_FTPERP] = expf(-red[0]);
        if (b == 0) {
            double mcl = g_loss[0] / ((double)NQ_CL * TOPK * CDIM);
            double mft = g_loss[1] / ((double)NQ_FT * TOPK * CDIM);
            out[OFF_LOSS] = (float)(0.25 * mft + 0.25 * mcl);
        }
    }
}

// ---------------------------------------------------------------------------
extern "C" void kernel_launch(void* const* d_in, const int* in_sizes, int n_in,
                              void* d_out, int out_size) {
    const float* feats = (const float*)d_in[0];   // (197,128,768)
    const float* clsE  = (const float*)d_in[1];   // (4096,768)
    const float* ftE   = (const float*)d_in[2];   // (4096,768)
    float* out = (float*)d_out;

    const int SMEM_GEMM = 67584;   // max(3*20480 staging, 128*132*4 epilogue)
    cudaFuncSetAttribute(gemm_wmma, cudaFuncAttributeMaxDynamicSharedMemorySize, SMEM_GEMM);

    init_kernel<<<(KTOT + 255) / 256, 256>>>();
    conv_norms_kernel<<<NQ_TOT + 2 * KCB, 256>>>(feats, clsE, ftE);

    __nv_bfloat16 *qbf, *cbf, *fbf;
    float *qnorm, *enorm;
    cudaGetSymbolAddress((void**)&qbf, g_qbf);
    cudaGetSymbolAddress((void**)&cbf, g_cbf);
    cudaGetSymbolAddress((void**)&fbf, g_fbf);
    cudaGetSymbolAddress((void**)&qnorm, g_qnorm);
    cudaGetSymbolAddress((void**)&enorm, g_enorm);

    // Unified GEMM: bm 0 = class tile, bm 1..196 = feat tiles.
    gemm_wmma<<<dim3(197, 32), 128, SMEM_GEMM>>>(
        qbf, cbf, fbf, qnorm, enorm, out + OFF_DIST);

    topk_kernel<<<NQ_TOT, 128>>>(out);
    rescore_pairs<<<(NQ_TOT * NCAND + 255) / 256, 256>>>(feats, clsE, ftE);
    select_kernel<<<(NQ_TOT + 255) / 256, 256>>>(out);
    gather_loss<<<NQ_TOT * TOPK / 8, 256>>>(feats, clsE, ftE, out + OFF_QUANT);
    finalize_kernel<<<2, 1024>>>(out);
}

// round 16
// speedup vs baseline: 1.1225x; 1.0391x over previous
#include <cuda_runtime.h>
#include <cuda_bf16.h>
#include <mma.h>
#include <math.h>
#include <float.h>
#include <stdint.h>

using namespace nvcuda;

// Problem constants
#define NQ_TOT   25216
#define NQ_CL    128
#define NQ_FT    25088
#define CDIM     768
#define KCB      4096
#define KTOT     8192
#define TOPK     3
#define NCAND    16

// Output offsets (flattened tuple, all float32)
#define OFF_LOSS    0LL
#define OFF_QUANT   1LL
#define OFF_CLPERP  58097665LL
#define OFF_FTPERP  58097666LL
#define OFF_CLAVG   58097667LL
#define OFF_FTAVG   58101763LL
#define OFF_IDX     58105859LL
#define OFF_DIST    58181507LL   // not 16B-aligned: scalar access only in dist region

// ---------------------------------------------------------------------------
// Scratch (device globals — no allocation allowed)
__device__ __nv_bfloat16 g_qbf[(size_t)NQ_TOT * CDIM];
__device__ __nv_bfloat16 g_cbf[(size_t)KCB * CDIM];
__device__ __nv_bfloat16 g_fbf[(size_t)KCB * CDIM];
__device__ float  g_qnorm[NQ_TOT];
__device__ float  g_enorm[KTOT];          // [0..4095]=class, [4096..]=feat
__device__ int    g_cand[NQ_TOT * NCAND]; // approx top-16 raw indices
__device__ float  g_rd[NQ_TOT * NCAND];   // exact fp32 rescored distances
__device__ int    g_idx[NQ_TOT * TOPK];   // exact top-3 raw indices
__device__ float  g_cnt[KTOT];
__device__ double g_loss[2];

// ---------------------------------------------------------------------------
__device__ __forceinline__ void cp16(void* s, const void* g) {
    uint32_t sa = (uint32_t)__cvta_generic_to_shared(s);
    asm volatile("cp.async.cg.shared.global [%0], [%1], 16;" :: "r"(sa), "l"(g));
}
#define CP_COMMIT() asm volatile("cp.async.commit_group;" ::: "memory")
#define CP_WAIT2()  asm volatile("cp.async.wait_group 2;" ::: "memory")

// ---------------------------------------------------------------------------
__global__ void init_kernel() {
    int t = blockIdx.x * blockDim.x + threadIdx.x;
    if (t < KTOT) g_cnt[t] = 0.0f;
    if (t < 2) g_loss[t] = 0.0;
}

// Fused: fp32 -> bf16 conversion AND row L2-norms (one read pass).
__global__ void conv_norms_kernel(const float* __restrict__ feats,
                                  const float* __restrict__ clsE,
                                  const float* __restrict__ ftE) {
    int row = blockIdx.x;
    const float* src; float* ndst; __nv_bfloat16* bdst;
    if (row < NQ_TOT) {
        src = feats + (size_t)row * CDIM; ndst = g_qnorm + row; bdst = g_qbf + (size_t)row * CDIM;
    } else if (row < NQ_TOT + KCB) {
        int r = row - NQ_TOT;
        src = clsE + (size_t)r * CDIM; ndst = g_enorm + r; bdst = g_cbf + (size_t)r * CDIM;
    } else {
        int r = row - NQ_TOT - KCB;
        src = ftE + (size_t)r * CDIM; ndst = g_enorm + KCB + r; bdst = g_fbf + (size_t)r * CDIM;
    }
    int t = threadIdx.x;  // 256
    float s = 0.f;
    #pragma unroll
    for (int i = t; i < CDIM; i += 256) {
        float v = src[i];
        bdst[i] = __float2bfloat16(v);
        s = fmaf(v, v, s);
    }
    __shared__ float red[256];
    red[t] = s; __syncthreads();
    for (int st = 128; st > 0; st >>= 1) { if (t < st) red[t] += red[t + st]; __syncthreads(); }
    if (t == 0) *ndst = red[0];
}

// ---------------------------------------------------------------------------
// bf16 WMMA GEMM + distance epilogue + fused FLT_MAX padding fill.
// grid (197, 32): bm==0 -> class tile, bm>=1 -> feat tile.
// CTA tile 128x128, 4 warps (64x64 warp tile), BK=32, cp.async 4-stage,
// 2 CTAs/SM (co-residency beats traffic reduction here — R14 lesson).
#define BK     32
#define LDS_   40     // bf16 row stride (80B, 16B-aligned)
#define NCHK   (CDIM / BK)   // 24
#define STAGEB 20480  // bytes per stage (A 10240 + B 10240)
#define NSTAGE 4

__global__ void __launch_bounds__(128, 2)
gemm_wmma(const __nv_bfloat16* __restrict__ Q,
          const __nv_bfloat16* __restrict__ Ccls,
          const __nv_bfloat16* __restrict__ Cft,
          const float* __restrict__ qn, const float* __restrict__ en,
          float* __restrict__ dist /* out + OFF_DIST */)
{
    extern __shared__ char smem[];
    const int tid = threadIdx.x;
    const int wid = tid >> 5;
    const int bm = blockIdx.x, bn = blockIdx.y;
    const int wm = wid & 1;
    const int wn = wid >> 1;

    const __nv_bfloat16* Abase = Q + (size_t)bm * 128 * CDIM;
    const __nv_bfloat16* Bbase = ((bm == 0) ? Ccls : Cft) + (size_t)bn * 128 * CDIM;
    const int colOff = (bm == 0) ? 0 : KCB;

    int lrow[4], lc8[4];
    #pragma unroll
    for (int v = 0; v < 4; v++) { int u = tid + v * 128; lrow[v] = u >> 2; lc8[v] = u & 3; }

    wmma::fragment<wmma::accumulator, 16, 16, 16, float> acc[4][4];
    #pragma unroll
    for (int i = 0; i < 4; i++)
        #pragma unroll
        for (int j = 0; j < 4; j++) wmma::fill_fragment(acc[i][j], 0.0f);

    // prefetch stages 0..2
    #pragma unroll
    for (int p = 0; p < 3; p++) {
        char* sA = smem + p * STAGEB;
        char* sB = sA + 10240;
        const int kk = p * BK;
        #pragma unroll
        for (int v = 0; v < 4; v++) {
            cp16(sA + (lrow[v] * LDS_ + lc8[v] * 8) * 2, Abase + (size_t)lrow[v] * CDIM + kk + lc8[v] * 8);
            cp16(sB + (lrow[v] * LDS_ + lc8[v] * 8) * 2, Bbase + (size_t)lrow[v] * CDIM + kk + lc8[v] * 8);
        }
        CP_COMMIT();
    }

    for (int c = 0; c < NCHK; c++) {
        const int s = c % NSTAGE;
        CP_WAIT2();            // chunk c's group complete (<=2 groups pending)
        __syncthreads();       // all warps done reading the slot we overwrite

        __nv_bfloat16* sA = (__nv_bfloat16*)(smem + s * STAGEB);
        __nv_bfloat16* sB = (__nv_bfloat16*)(smem + s * STAGEB + 10240);

        #pragma unroll
        for (int kk = 0; kk < BK / 16; kk++) {
            wmma::fragment<wmma::matrix_a, 16, 16, 16, __nv_bfloat16, wmma::row_major> af[4];
            wmma::fragment<wmma::matrix_b, 16, 16, 16, __nv_bfloat16, wmma::col_major> bf[4];
            #pragma unroll
            for (int i = 0; i < 4; i++)
                wmma::load_matrix_sync(af[i], sA + (wm * 64 + i * 16) * LDS_ + kk * 16, LDS_);
            #pragma unroll
            for (int j = 0; j < 4; j++)
                wmma::load_matrix_sync(bf[j], sB + (wn * 64 + j * 16) * LDS_ + kk * 16, LDS_);
            #pragma unroll
            for (int i = 0; i < 4; i++)
                #pragma unroll
                for (int j = 0; j < 4; j++)
                    wmma::mma_sync(acc[i][j], af[i], bf[j], acc[i][j]);
        }

        if (c + 3 < NCHK) {
            const int ns = (c + 3) % NSTAGE;
            char* nA = smem + ns * STAGEB;
            char* nB = nA + 10240;
            const int kk = (c + 3) * BK;
            #pragma unroll
            for (int v = 0; v < 4; v++) {
                cp16(nA + (lrow[v] * LDS_ + lc8[v] * 8) * 2, Abase + (size_t)lrow[v] * CDIM + kk + lc8[v] * 8);
                cp16(nB + (lrow[v] * LDS_ + lc8[v] * 8) * 2, Bbase + (size_t)lrow[v] * CDIM + kk + lc8[v] * 8);
            }
        }
        CP_COMMIT();           // one group per iteration keeps the count model
    }
    __syncthreads();

    // Epilogue: acc -> smem (f32, ld=132) -> coalesced scalar stores + padding
    float* sf = (float*)smem;   // 128*132*4 = 67584 <= 81920
    #pragma unroll
    for (int i = 0; i < 4; i++)
        #pragma unroll
        for (int j = 0; j < 4; j++)
            wmma::store_matrix_sync(sf + (size_t)(wm * 64 + i * 16) * 132 + wn * 64 + j * 16,
                                    acc[i][j], 132, wmma::mem_row_major);
    __syncthreads();

    const int colL = tid;
    const int colG = bn * 128 + colL;
    const float env = en[colOff + colG];
    const long long cReal = (long long)(colOff + colG);
    const long long cPad  = (long long)((colOff ^ KCB) + colG);
    #pragma unroll 4
    for (int r = 0; r < 128; r++) {
        const long long rbase = (long long)(bm * 128 + r) * KTOT;
        dist[rbase + cReal] = qn[bm * 128 + r] + env - 2.0f * sf[(size_t)r * 132 + colL];
        dist[rbase + cPad]  = FLT_MAX;
    }
}

// ---------------------------------------------------------------------------
// Approximate top-16 per query row, u32 packed keys (R13 block version —
// measured best). key = (dist_bits & 0xFFFFF000) | idx; positive fp32 bit
// order == numeric order; truncation noise absorbed by the exact rescore;
// u32 min == lower-index tie-break. Owner-only removal per round.
__global__ void __launch_bounds__(128)
topk_kernel(const float* __restrict__ out) {
    int q = blockIdx.x;
    int t = threadIdx.x;
    const float* row = out + OFF_DIST + (long long)q * KTOT + (q < NQ_CL ? 0 : KCB);

    unsigned key[32];
    #pragma unroll
    for (int j = 0; j < 32; j++) {
        unsigned vb = __float_as_uint(row[j * 128 + t]);
        key[j] = (vb & 0xFFFFF000u) | (unsigned)(j * 128 + t);
    }
    unsigned lm = key[0];
    #pragma unroll
    for (int j = 1; j < 32; j++) lm = min(lm, key[j]);

    __shared__ unsigned wmin[4];
    __shared__ unsigned win;

    for (int sel = 0; sel < NCAND; sel++) {
        unsigned m = lm;
        #pragma unroll
        for (int o = 16; o; o >>= 1)
            m = min(m, __shfl_xor_sync(0xffffffffu, m, o));
        if ((t & 31) == 0) wmin[t >> 5] = m;
        __syncthreads();
        if (t == 0) {
            unsigned mm = min(min(wmin[0], wmin[1]), min(wmin[2], wmin[3]));
            win = mm;
            g_cand[q * NCAND + sel] = (int)(mm & 0xFFFu);
        }
        __syncthreads();
        unsigned widx = win & 0xFFFu;
        if ((widx & 127u) == (unsigned)t) {
            key[widx >> 7] = 0xFFFFFFFFu;
            lm = key[0];
            #pragma unroll
            for (int j = 1; j < 32; j++) lm = min(lm, key[j]);
        }
    }
}

// ---------------------------------------------------------------------------
// Exact fp32 rescore: sequential fmaf over k in index order — bit-identical
// to the fp32 GEMM ordering that matched jax exactly.
__global__ void __launch_bounds__(256)
rescore_pairs(const float* __restrict__ feats,
              const float* __restrict__ clsE, const float* __restrict__ ftE) {
    int g = blockIdx.x * 256 + threadIdx.x;
    if (g >= NQ_TOT * NCAND) return;
    int q = g / NCAND;
    int cand = g_cand[g];
    const float4* x = (const float4*)(feats + (size_t)q * CDIM);
    const float4* e = (const float4*)((q < NQ_CL ? clsE : ftE) + (size_t)cand * CDIM);
    float s = 0.f;
    #pragma unroll 8
    for (int i = 0; i < CDIM / 4; i++) {
        float4 a = x[i], b = e[i];
        s = fmaf(a.x, b.x, s);
        s = fmaf(a.y, b.y, s);
        s = fmaf(a.z, b.z, s);
        s = fmaf(a.w, b.w, s);
    }
    g_rd[g] = (g_qnorm[q] + g_enorm[(q < NQ_CL ? 0 : KCB) + cand]) - 2.f * s;
}

// Final top-3 from exact distances, lower-index tie-break; counts + idx output
__global__ void __launch_bounds__(256)
select_kernel(float* __restrict__ out) {
    int q = blockIdx.x * 256 + threadIdx.x;
    if (q >= NQ_TOT) return;
    float d[NCAND]; int id[NCAND]; bool used[NCAND];
    #pragma unroll
    for (int c = 0; c < NCAND; c++) {
        d[c] = g_rd[q * NCAND + c];
        id[c] = g_cand[q * NCAND + c];
        used[c] = false;
    }
    int base = (q < NQ_CL ? 0 : KCB);
    for (int sel = 0; sel < TOPK; sel++) {
        float bv = FLT_MAX; int bi = 0x7fffffff; int bw = 0;
        #pragma unroll
        for (int c = 0; c < NCAND; c++) {
            if (used[c]) continue;
            if (d[c] < bv || (d[c] == bv && id[c] < bi)) { bv = d[c]; bi = id[c]; bw = c; }
        }
        used[bw] = true;
        g_idx[q * TOPK + sel] = bi;
        out[OFF_IDX + q * TOPK + sel] = (float)(bi + base);
        atomicAdd(&g_cnt[base + bi], 1.0f);
    }
}

// Gather quantized = emb[idx] + commitment-loss sums. One WARP per gather.
__global__ void __launch_bounds__(256)
gather_loss(const float* __restrict__ feats,
            const float* __restrict__ clsE, const float* __restrict__ ftE,
            float* __restrict__ outQ) {
    int wid  = threadIdx.x >> 5;
    int lane = threadIdx.x & 31;
    int g = blockIdx.x * 8 + wid;         // 75648 = 9456*8 exactly
    int q = g / TOPK;
    int idx = g_idx[g];
    const float* x = feats + (size_t)q * CDIM;
    const float* e = (q < NQ_CL ? clsE : ftE) + (size_t)idx * CDIM;
    float s = 0.f;
    #pragma unroll
    for (int i = lane; i < CDIM; i += 32) {
        float ev = e[i];
        float d = ev - x[i];
        outQ[(size_t)g * CDIM + i] = ev;
        s = fmaf(d, d, s);
    }
    #pragma unroll
    for (int o = 16; o; o >>= 1) s += __shfl_xor_sync(0xffffffffu, s, o);

    __shared__ float ws[8];
    __shared__ int   wb[8];
    if (lane == 0) { ws[wid] = s; wb[wid] = (q < NQ_CL) ? 0 : 1; }
    __syncthreads();
    if (threadIdx.x == 0) {
        double s0 = 0.0, s1 = 0.0; bool h0 = false, h1 = false;
        #pragma unroll
        for (int w = 0; w < 8; w++) {
            if (wb[w]) { s1 += (double)ws[w]; h1 = true; }
            else       { s0 += (double)ws[w]; h0 = true; }
        }
        if (h0) atomicAdd(&g_loss[0], s0);
        if (h1) atomicAdd(&g_loss[1], s1);
    }
}

// avg_probs, perplexities, loss scalar
__global__ void __launch_bounds__(1024)
finalize_kernel(float* __restrict__ out) {
    int b = blockIdx.x;
    int t = threadIdx.x;
    float N = (b == 0) ? (float)NQ_CL : (float)NQ_FT;
    float* avg = out + (b == 0 ? OFF_CLAVG : OFF_FTAVG);
    float ent = 0.f;
    for (int i = t; i < KCB; i += 1024) {
        float p = g_cnt[b * KCB + i] / N;
        avg[i] = p;
        ent += p * logf(p + 1e-10f);
    }
    __shared__ float red[1024];
    red[t] = ent; __syncthreads();
    for (int st = 512; st > 0; st >>= 1) { if (t < st) red[t] += red[t + st]; __syncthreads(); }
    if (t == 0) {
        out[b == 0 ? OFF_CLPERP : OFF_FTPERP] = expf(-red[0]);
        if (b == 0) {
            double mcl = g_loss[0] / ((double)NQ_CL * TOPK * CDIM);
            double mft = g_loss[1] / ((double)NQ_FT * TOPK * CDIM);
            out[OFF_LOSS] = (float)(0.25 * mft + 0.25 * mcl);
        }
    }
}

// ---------------------------------------------------------------------------
extern "C" void kernel_launch(void* const* d_in, const int* in_sizes, int n_in,
                              void* d_out, int out_size) {
    const float* feats = (const float*)d_in[0];   // (197,128,768)
    const float* clsE  = (const float*)d_in[1];   // (4096,768)
    const float* ftE   = (const float*)d_in[2];   // (4096,768)
    float* out = (float*)d_out;

    const int SMEM_GEMM = NSTAGE * STAGEB;   // 81920
    cudaFuncSetAttribute(gemm_wmma, cudaFuncAttributeMaxDynamicSharedMemorySize, SMEM_GEMM);

    init_kernel<<<(KTOT + 255) / 256, 256>>>();
    conv_norms_kernel<<<NQ_TOT + 2 * KCB, 256>>>(feats, clsE, ftE);

    __nv_bfloat16 *qbf, *cbf, *fbf;
    float *qnorm, *enorm;
    cudaGetSymbolAddress((void**)&qbf, g_qbf);
    cudaGetSymbolAddress((void**)&cbf, g_cbf);
    cudaGetSymbolAddress((void**)&fbf, g_fbf);
    cudaGetSymbolAddress((void**)&qnorm, g_qnorm);
    cudaGetSymbolAddress((void**)&enorm, g_enorm);

    // Unified GEMM: bm 0 = class tile, bm 1..196 = feat tiles.
    gemm_wmma<<<dim3(197, 32), 128, SMEM_GEMM>>>(
        qbf, cbf, fbf, qnorm, enorm, out + OFF_DIST);

    topk_kernel<<<NQ_TOT, 128>>>(out);
    rescore_pairs<<<(NQ_TOT * NCAND + 255) / 256, 256>>>(feats, clsE, ftE);
    select_kernel<<<(NQ_TOT + 255) / 256, 256>>>(out);
    gather_loss<<<NQ_TOT * TOPK / 8, 256>>>(feats, clsE, ftE, out + OFF_QUANT);
    finalize_kernel<<<2, 1024>>>(out);
}